// round 16
// baseline (speedup 1.0000x reference)
#include <cuda_runtime.h>
#include <cstdint>

#define Bq 32
#define Sq 256
#define Eq 256
#define Hq 512
#define Gq 2048
#define M_TOT (Bq * Sq)

#define TPB 512
#define HP2 516                     // staged row stride (floats)
#define SM_X    0                   // xsh 32*516
#define SM_H    (32 * HP2)          // hsh 32*516
#define SM_PART (64 * HP2)          // part 256*33
#define SM_BIAS (SM_PART + 256 * 33)
#define SMEM_FLOATS (SM_BIAS + 64)
#define SMEM_BYTES  (SMEM_FLOATS * 4)

typedef unsigned long long ull;

#define FMA2(acc, a, b) \
    asm("fma.rn.f32x2 %0, %1, %2, %0;" : "+l"(acc) : "l"(a), "l"(b))
#define UNPK2(lo, hi, v) \
    asm("mov.b64 {%0, %1}, %2;" : "=f"(lo), "=f"(hi) : "l"(v))

__device__ __forceinline__ float fsigmoid(float x) {
    return __fdividef(1.f, 1.f + __expf(-x));
}
__device__ __forceinline__ float ftanh(float x) {
    float e = __expf(2.f * x);
    return 1.f - __fdividef(2.f, e + 1.f);
}

// ---------------- device scratch ----------------
__device__ float g_Wt[4 * 32 * 2 * 2 * 64 * 64 * 4];  // 32MB transposed W
__device__ float g_ring[4][4][Bq * Hq];               // per-layer h rings [b][k]
__device__ float g_out3[M_TOT * Hq];
__device__ float g_probs[M_TOT * Hq];
__device__ unsigned g_flg[4][32 * 32];                // per-layer per-CTA flags

// ---- weight transpose (per replay) + flag zeroing ----
// Wt block (l,c,m,kh) = 4096 float4; element (i,r) at i*64 + r.
__global__ void __launch_bounds__(256) transpose_kernel(
    const float* __restrict__ Wih0, const float* __restrict__ WihR,
    const float* __restrict__ Whh)
{
    int tid = threadIdx.x;
    if (blockIdx.x == 0) {
        unsigned* f = &g_flg[0][0];
        for (int i = tid; i < 4 * 32 * 32; i += 256) f[i] = 0u;
    }
    unsigned v = blockIdx.x * 256 + tid;       // 0 .. 2^21-1
    int r  = v & 63;  v >>= 6;
    int i  = v & 63;  v >>= 6;
    int h2 = v & 1;   v >>= 1;
    int m  = v & 1;   v >>= 1;
    int c  = v & 31;  v >>= 5;
    int l  = v;                                 // 0..3
    int grow = (r >> 4) * Hq + c * 16 + (r & 15);
    float4 val = make_float4(0.f, 0.f, 0.f, 0.f);
    if (m == 0) {
        val = *reinterpret_cast<const float4*>(
            Whh + (size_t)l * Gq * Hq + (size_t)grow * Hq + h2 * 256 + i * 4);
    } else if (l > 0) {
        val = *reinterpret_cast<const float4*>(
            WihR + (size_t)(l - 1) * Gq * Hq + (size_t)grow * Hq + h2 * 256 + i * 4);
    } else if (i < 32) {
        val = *reinterpret_cast<const float4*>(
            Wih0 + (size_t)grow * Eq + h2 * 128 + i * 4);
    }
    size_t idx4 = ((size_t)(((l * 32 + c) * 2 + m) * 2 + h2)) * 4096 + i * 64 + r;
    reinterpret_cast<float4*>(g_Wt)[idx4] = val;
}

// ---- fused 4-layer pipelined LSTM: 128 CTAs = 4 layers x 32 CTAs ----
// 512 threads: 16 dot-warps = (m, kh, rq); lane = (r16, bh).
// Lane owns 1 row x 16 batches (b = 2j+bh) -> acc[16].
__global__ void __launch_bounds__(TPB) lstm_fused_kernel(
    const float* __restrict__ x,     // [b][s][256]
    const float* __restrict__ bih, const float* __restrict__ bhh,
    float* __restrict__ out3)
{
    extern __shared__ float sm[];
    float* xsh  = sm + SM_X;
    float* hsh  = sm + SM_H;
    float* part = sm + SM_PART;
    float* bsh  = sm + SM_BIAS;

    const int tid  = threadIdx.x;
    const int l    = blockIdx.x >> 5;
    const int cidx = blockIdx.x & 31;
    const int j0   = cidx * 16;
    const int wid  = tid >> 5;
    const int lane = tid & 31;

    if (tid < 64) {
        int grow = (tid >> 4) * Hq + j0 + (tid & 15);
        bsh[tid] = bih[l * Gq + grow] + bhh[l * Gq + grow];
    }

    // dot-role constants
    const int m   = wid >> 3;                 // 0=Whh.h, 1=Wih.x
    const int kh  = (wid >> 2) & 1;           // k-half
    const int rq  = wid & 3;                  // row quad
    const int r16 = lane >> 1;
    const int bh  = lane & 1;                 // batch parity
    const int row = rq * 16 + r16;            // local row 0..63
    const int nk4  = (m == 1 && l == 0) ? 32 : 64;
    const int koff = kh * ((m == 1 && l == 0) ? 128 : 256);
    const int m2h  = m * 2 + kh;
    const ulonglong2* wtp = reinterpret_cast<const ulonglong2*>(g_Wt) +
        ((size_t)(((l * 32 + cidx) * 2 + m) * 2 + kh)) * 4096 + row;

    // gate-role constants (1 item per thread)
    const int col = tid & 15;
    const int bg  = (tid >> 4) & 31;
    float c0 = 0.f;

    unsigned* flg_own = &g_flg[l][0];
    const unsigned* flg_up = (l > 0) ? &g_flg[l - 1][0] : 0;
    const unsigned* flg_dn = (l < 3) ? &g_flg[l + 1][0] : 0;

    for (int t = 0; t < Sq; ++t) {
        // ---- waits (warps 0/1/2 poll in parallel) ----
        if (wid == 0 && t > 0) {
            const unsigned* f = flg_own + lane * 32; unsigned s = 0u;
            do { if (!s) { unsigned q;
                asm volatile("ld.relaxed.gpu.global.u32 %0,[%1];":"=r"(q):"l"(f));
                s = (q >= (unsigned)t); } } while (__all_sync(~0u, s) == 0);
        }
        if (wid == 1 && l > 0) {
            const unsigned* f = flg_up + lane * 32; unsigned s = 0u;
            do { if (!s) { unsigned q;
                asm volatile("ld.relaxed.gpu.global.u32 %0,[%1];":"=r"(q):"l"(f));
                s = (q >= (unsigned)(t + 1)); } } while (__all_sync(~0u, s) == 0);
        }
        if (wid == 2 && l < 3 && t >= 4) {
            const unsigned* f = flg_dn + lane * 32; unsigned s = 0u;
            do { if (!s) { unsigned q;
                asm volatile("ld.relaxed.gpu.global.u32 %0,[%1];":"=r"(q):"l"(f));
                s = (q >= (unsigned)(t - 3)); } } while (__all_sync(~0u, s) == 0);
        }
        __syncthreads();

        // ---- stage h_own(t-1) and x(t) ----
        if (t > 0) {
            const float4* hs = reinterpret_cast<const float4*>(g_ring[l][(t - 1) & 3]);
#pragma unroll
            for (int p = 0; p < 8; ++p) {
                int q = p * TPB + tid, b = q >> 7, kq = q & 127;
                *reinterpret_cast<float4*>(hsh + b * HP2 + kq * 4) = __ldcg(hs + q);
            }
        }
        if (l == 0) {
#pragma unroll
            for (int p = 0; p < 4; ++p) {
                int q = p * TPB + tid, b = q >> 6, kq = q & 63;
                *reinterpret_cast<float4*>(xsh + b * HP2 + kq * 4) =
                    __ldg(reinterpret_cast<const float4*>(
                        x + (size_t)b * Sq * Eq + (size_t)t * Eq) + kq);
            }
        } else {
            const float4* xs = reinterpret_cast<const float4*>(g_ring[l - 1][t & 3]);
#pragma unroll
            for (int p = 0; p < 8; ++p) {
                int q = p * TPB + tid, b = q >> 7, kq = q & 127;
                *reinterpret_cast<float4*>(xsh + b * HP2 + kq * 4) = __ldcg(xs + q);
            }
        }
        __syncthreads();

        // ---- dot: lane = (row, bh); acc over 16 batches (b = 2j+bh) ----
        if (m == 0 && t == 0) {
#pragma unroll
            for (int j = 0; j < 16; ++j)
                part[(m2h * 64 + row) * 33 + 2 * j + bh] = 0.f;
        } else {
            const float* base = (m ? xsh : hsh) + koff + bh * HP2;
            ull acc[16];
#pragma unroll
            for (int j = 0; j < 16; ++j) acc[j] = 0ull;

            ulonglong2 wv_a = __ldg(wtp);
            ulonglong2 wv_b = __ldg(wtp + 64);
            for (int i = 0; i < nk4; ++i) {
                ulonglong2 wv = wv_a;
                wv_a = wv_b;
                if (i + 2 < nk4) wv_b = __ldg(wtp + (size_t)(i + 2) * 64);
                const float* hb = base + i * 4;
#pragma unroll
                for (int j = 0; j < 16; ++j) {
                    ulonglong2 hv =
                        *reinterpret_cast<const ulonglong2*>(hb + 2 * j * HP2);
                    FMA2(acc[j], hv.x, wv.x);
                    FMA2(acc[j], hv.y, wv.y);
                }
            }
#pragma unroll
            for (int j = 0; j < 16; ++j) {
                float lo, hi; UNPK2(lo, hi, acc[j]);
                part[(m2h * 64 + row) * 33 + 2 * j + bh] = lo + hi;
            }
        }
        __syncthreads();

        // ---- gates: one (col, bg) item per thread ----
        {
            float* ringw = g_ring[l][t & 3];
            float s0 = 0.f, s1 = 0.f, s2 = 0.f, s3 = 0.f;
#pragma unroll
            for (int q = 0; q < 4; ++q) {
                s0 += part[(q * 64 +      col) * 33 + bg];
                s1 += part[(q * 64 + 16 + col) * 33 + bg];
                s2 += part[(q * 64 + 32 + col) * 33 + bg];
                s3 += part[(q * 64 + 48 + col) * 33 + bg];
            }
            float si = fsigmoid(s0 + bsh[col]);
            float sf = fsigmoid(s1 + bsh[16 + col]);
            float tg = ftanh(s2 + bsh[32 + col]);
            float so = fsigmoid(s3 + bsh[48 + col]);
            c0 = sf * c0 + si * tg;
            float hn = so * ftanh(c0);
            ringw[(size_t)bg * Hq + j0 + col] = hn;
            if (l == 3)
                out3[((size_t)bg * Sq + t) * Hq + j0 + col] = hn;
        }
        __syncthreads();
        if (tid == 0) {
            unsigned val = (unsigned)(t + 1);
            asm volatile("membar.gl;" ::: "memory");
            asm volatile("st.release.gpu.global.u32 [%0], %1;"
                         :: "l"(&flg_own[cidx * 32]), "r"(val) : "memory");
        }
    }
}

// ---- softmax over sequence axis ----
__global__ void __launch_bounds__(256) softmax_kernel(
    const float* __restrict__ in, float* __restrict__ probs)
{
    int gw = (blockIdx.x * 256 + threadIdx.x) >> 5;
    int lane = threadIdx.x & 31;
    int bb = gw >> 9, hh = gw & 511;
    const float* p = in + (size_t)bb * Sq * Hq + hh;
    float v[8], mx = -3.4e38f;
#pragma unroll
    for (int i = 0; i < 8; ++i) {
        v[i] = p[(size_t)(lane + 32 * i) * Hq];
        mx = fmaxf(mx, v[i]);
    }
#pragma unroll
    for (int o = 16; o; o >>= 1) mx = fmaxf(mx, __shfl_xor_sync(~0u, mx, o));
    float sum = 0.f;
#pragma unroll
    for (int i = 0; i < 8; ++i) { v[i] = __expf(v[i] - mx); sum += v[i]; }
#pragma unroll
    for (int o = 16; o; o >>= 1) sum += __shfl_xor_sync(~0u, sum, o);
    float inv = 1.f / sum;
    float* q = probs + (size_t)bb * Sq * Hq + hh;
#pragma unroll
    for (int i = 0; i < 8; ++i) q[(size_t)(lane + 32 * i) * Hq] = v[i] * inv;
}

// ---- final FC ----
__global__ void __launch_bounds__(256) fc_kernel(
    const float* __restrict__ probs, const float* __restrict__ Wfc,
    const float* __restrict__ bfc, float* __restrict__ out)
{
    int gw = (blockIdx.x * 256 + threadIdx.x) >> 5;
    int lane = threadIdx.x & 31;
    const float* p = probs + (size_t)gw * Hq;
    float a0 = 0.f, a1 = 0.f, a2 = 0.f, a3 = 0.f;
    for (int k = lane; k < Hq; k += 32) {
        float pv = p[k];
        a0 += pv * Wfc[k];
        a1 += pv * Wfc[Hq + k];
        a2 += pv * Wfc[2 * Hq + k];
        a3 += pv * Wfc[3 * Hq + k];
    }
#pragma unroll
    for (int o = 16; o; o >>= 1) {
        a0 += __shfl_xor_sync(~0u, a0, o);
        a1 += __shfl_xor_sync(~0u, a1, o);
        a2 += __shfl_xor_sync(~0u, a2, o);
        a3 += __shfl_xor_sync(~0u, a3, o);
    }
    if (lane == 0) {
        float4 rr;
        rr.x = a0 + bfc[0]; rr.y = a1 + bfc[1];
        rr.z = a2 + bfc[2]; rr.w = a3 + bfc[3];
        *reinterpret_cast<float4*>(out + (size_t)gw * 4) = rr;
    }
}

// ---- launcher ----
extern "C" void kernel_launch(void* const* d_in, const int* in_sizes, int n_in,
                              void* d_out, int out_size)
{
    const float* x    = (const float*)d_in[0];
    const float* Wih0 = (const float*)d_in[1];
    const float* WihR = (const float*)d_in[2];
    const float* Whh  = (const float*)d_in[3];
    const float* bih  = (const float*)d_in[4];
    const float* bhh  = (const float*)d_in[5];
    const float* Wfc  = (const float*)d_in[6];
    const float* bfc  = (const float*)d_in[7];
    float* out = (float*)d_out;

    float *out3, *probs;
    cudaGetSymbolAddress((void**)&out3,  g_out3);
    cudaGetSymbolAddress((void**)&probs, g_probs);

    cudaFuncSetAttribute(lstm_fused_kernel,
                         cudaFuncAttributeMaxDynamicSharedMemorySize,
                         SMEM_BYTES);

    transpose_kernel<<<8192, 256>>>(Wih0, WihR, Whh);
    lstm_fused_kernel<<<128, TPB, SMEM_BYTES>>>(x, bih, bhh, out3);
    softmax_kernel<<<2048, 256>>>(out3, probs);
    fc_kernel<<<1024, 256>>>(probs, Wfc, bfc, out);
}

// round 17
// speedup vs baseline: 1.2049x; 1.2049x over previous
#include <cuda_runtime.h>
#include <cstdint>

#define Bq 32
#define Sq 256
#define Eq 256
#define Hq 512
#define Gq 2048
#define M_TOT (Bq * Sq)

#define TPB 256
#define HP2 516
#define SM_X    0
#define SM_H    (32 * HP2)
#define SM_PART (64 * HP2)
#define SM_BIAS (SM_PART + 256 * 33)
#define SMEM_FLOATS (SM_BIAS + 64)
#define SMEM_BYTES  (SMEM_FLOATS * 4)

typedef unsigned long long ull;

#define FMA2(acc, a, b) \
    asm("fma.rn.f32x2 %0, %1, %2, %0;" : "+l"(acc) : "l"(a), "l"(b))
#define UNPK2(lo, hi, v) \
    asm("mov.b64 {%0, %1}, %2;" : "=f"(lo), "=f"(hi) : "l"(v))

__device__ __forceinline__ float fsigmoid(float x) {
    return __fdividef(1.f, 1.f + __expf(-x));
}
__device__ __forceinline__ float ftanh(float x) {
    float e = __expf(2.f * x);
    return 1.f - __fdividef(2.f, e + 1.f);
}

// ---------------- device scratch ----------------
__device__ float g_Wt[4 * 32 * 2 * 2 * 64 * 64 * 4];  // 32MB transposed W
__device__ float g_ring[4][4][Bq * Hq];               // per-layer h rings [b][k]
__device__ float g_out3[M_TOT * Hq];
__device__ float g_probs[M_TOT * Hq];
__device__ unsigned g_flg[4][32 * 32];

// ---- weight transpose (per replay) + flag zeroing ----
__global__ void __launch_bounds__(256) transpose_kernel(
    const float* __restrict__ Wih0, const float* __restrict__ WihR,
    const float* __restrict__ Whh)
{
    int tid = threadIdx.x;
    if (blockIdx.x == 0) {
        unsigned* f = &g_flg[0][0];
        for (int i = tid; i < 4 * 32 * 32; i += 256) f[i] = 0u;
    }
    unsigned v = blockIdx.x * 256 + tid;
    int r  = v & 63;  v >>= 6;
    int i  = v & 63;  v >>= 6;
    int h2 = v & 1;   v >>= 1;
    int m  = v & 1;   v >>= 1;
    int c  = v & 31;  v >>= 5;
    int l  = v;
    int grow = (r >> 4) * Hq + c * 16 + (r & 15);
    float4 val = make_float4(0.f, 0.f, 0.f, 0.f);
    if (m == 0) {
        val = *reinterpret_cast<const float4*>(
            Whh + (size_t)l * Gq * Hq + (size_t)grow * Hq + h2 * 256 + i * 4);
    } else if (l > 0) {
        val = *reinterpret_cast<const float4*>(
            WihR + (size_t)(l - 1) * Gq * Hq + (size_t)grow * Hq + h2 * 256 + i * 4);
    } else if (i < 32) {
        val = *reinterpret_cast<const float4*>(
            Wih0 + (size_t)grow * Eq + h2 * 128 + i * 4);
    }
    size_t idx4 = ((size_t)(((l * 32 + c) * 2 + m) * 2 + h2)) * 4096 + i * 64 + r;
    reinterpret_cast<float4*>(g_Wt)[idx4] = val;
}

// ---- fused 4-layer pipelined LSTM: 128 CTAs = 4 layers x 32 CTAs ----
// 8 dot-warps = (m, kh, rw); lane (r16, bh) owns rows {rw*16+r16, +32},
// 16 batches (b = 2j+bh). Each hv LDS feeds 4 FMA2 (ratio 1:4).
__global__ void __launch_bounds__(TPB) lstm_fused_kernel(
    const float* __restrict__ x,
    const float* __restrict__ bih, const float* __restrict__ bhh,
    float* __restrict__ out3)
{
    extern __shared__ float sm[];
    float* xsh  = sm + SM_X;
    float* hsh  = sm + SM_H;
    float* part = sm + SM_PART;
    float* bsh  = sm + SM_BIAS;

    const int tid  = threadIdx.x;
    const int l    = blockIdx.x >> 5;
    const int cidx = blockIdx.x & 31;
    const int j0   = cidx * 16;
    const int wid  = tid >> 5;
    const int lane = tid & 31;

    if (tid < 64) {
        int grow = (tid >> 4) * Hq + j0 + (tid & 15);
        bsh[tid] = bih[l * Gq + grow] + bhh[l * Gq + grow];
    }

    // dot-role constants
    const int m    = wid >> 2;                // 0=Whh.h, 1=Wih.x
    const int kh   = (wid >> 1) & 1;          // k-half
    const int rw   = wid & 1;                 // row-half selector
    const int r16  = lane >> 1;
    const int bh   = lane & 1;
    const int row0 = rw * 16 + r16;           // 0..31
    const int row1 = row0 + 32;               // 32..63
    const int nk4  = (m == 1 && l == 0) ? 32 : 64;
    const int koff = kh * ((m == 1 && l == 0) ? 128 : 256);
    const int m2h  = m * 2 + kh;
    const ulonglong2* wb = reinterpret_cast<const ulonglong2*>(g_Wt) +
        ((size_t)(((l * 32 + cidx) * 2 + m) * 2 + kh)) * 4096;
    const ulonglong2* wtp0 = wb + row0;
    const ulonglong2* wtp1 = wb + row1;

    // gate-role constants (2 items: b=bg, b=bg+16)
    const int col = tid & 15;
    const int bg  = tid >> 4;
    float c0 = 0.f, c1 = 0.f;

    unsigned* flg_own = &g_flg[l][0];
    const unsigned* flg_up = (l > 0) ? &g_flg[l - 1][0] : 0;
    const unsigned* flg_dn = (l < 3) ? &g_flg[l + 1][0] : 0;

    for (int t = 0; t < Sq; ++t) {
        // ---- waits ----
        if (wid == 0 && t > 0) {
            const unsigned* f = flg_own + lane * 32; unsigned s = 0u;
            do { if (!s) { unsigned q;
                asm volatile("ld.relaxed.gpu.global.u32 %0,[%1];":"=r"(q):"l"(f));
                s = (q >= (unsigned)t); } } while (__all_sync(~0u, s) == 0);
        }
        if (wid == 1 && l > 0) {
            const unsigned* f = flg_up + lane * 32; unsigned s = 0u;
            do { if (!s) { unsigned q;
                asm volatile("ld.relaxed.gpu.global.u32 %0,[%1];":"=r"(q):"l"(f));
                s = (q >= (unsigned)(t + 1)); } } while (__all_sync(~0u, s) == 0);
        }
        if (wid == 2 && l < 3 && t >= 4) {
            const unsigned* f = flg_dn + lane * 32; unsigned s = 0u;
            do { if (!s) { unsigned q;
                asm volatile("ld.relaxed.gpu.global.u32 %0,[%1];":"=r"(q):"l"(f));
                s = (q >= (unsigned)(t - 3)); } } while (__all_sync(~0u, s) == 0);
        }
        __syncthreads();

        // ---- stage h_own(t-1) and x(t) ----
        if (t > 0) {
            const float4* hs = reinterpret_cast<const float4*>(g_ring[l][(t - 1) & 3]);
#pragma unroll
            for (int p = 0; p < 16; ++p) {
                int q = p * TPB + tid, b = q >> 7, kq = q & 127;
                *reinterpret_cast<float4*>(hsh + b * HP2 + kq * 4) = __ldcg(hs + q);
            }
        }
        if (l == 0) {
#pragma unroll
            for (int p = 0; p < 8; ++p) {
                int q = p * TPB + tid, b = q >> 6, kq = q & 63;
                *reinterpret_cast<float4*>(xsh + b * HP2 + kq * 4) =
                    __ldg(reinterpret_cast<const float4*>(
                        x + (size_t)b * Sq * Eq + (size_t)t * Eq) + kq);
            }
        } else {
            const float4* xs = reinterpret_cast<const float4*>(g_ring[l - 1][t & 3]);
#pragma unroll
            for (int p = 0; p < 16; ++p) {
                int q = p * TPB + tid, b = q >> 7, kq = q & 127;
                *reinterpret_cast<float4*>(xsh + b * HP2 + kq * 4) = __ldcg(xs + q);
            }
        }
        __syncthreads();

        // ---- dot: 2 rows x 16 batches per lane ----
        if (m == 0 && t == 0) {
#pragma unroll
            for (int j = 0; j < 16; ++j) {
                part[(m2h * 64 + row0) * 33 + 2 * j + bh] = 0.f;
                part[(m2h * 64 + row1) * 33 + 2 * j + bh] = 0.f;
            }
        } else {
            const float* base = (m ? xsh : hsh) + koff + bh * HP2;
            ull acc0[16], acc1[16];
#pragma unroll
            for (int j = 0; j < 16; ++j) { acc0[j] = 0ull; acc1[j] = 0ull; }

            ulonglong2 a0 = __ldg(wtp0), a1 = __ldg(wtp0 + 64);
            ulonglong2 b0 = __ldg(wtp1), b1 = __ldg(wtp1 + 64);
            for (int i = 0; i < nk4; ++i) {
                ulonglong2 w0 = a0, w1 = b0;
                a0 = a1; b0 = b1;
                if (i + 2 < nk4) {
                    a1 = __ldg(wtp0 + (size_t)(i + 2) * 64);
                    b1 = __ldg(wtp1 + (size_t)(i + 2) * 64);
                }
                const float* hb = base + i * 4;
#pragma unroll
                for (int j = 0; j < 16; ++j) {
                    ulonglong2 hv =
                        *reinterpret_cast<const ulonglong2*>(hb + 2 * j * HP2);
                    FMA2(acc0[j], hv.x, w0.x);
                    FMA2(acc0[j], hv.y, w0.y);
                    FMA2(acc1[j], hv.x, w1.x);
                    FMA2(acc1[j], hv.y, w1.y);
                }
            }
#pragma unroll
            for (int j = 0; j < 16; ++j) {
                float lo, hi;
                UNPK2(lo, hi, acc0[j]);
                part[(m2h * 64 + row0) * 33 + 2 * j + bh] = lo + hi;
                UNPK2(lo, hi, acc1[j]);
                part[(m2h * 64 + row1) * 33 + 2 * j + bh] = lo + hi;
            }
        }
        __syncthreads();

        // ---- gates: (col, bg) and (col, bg+16) ----
        {
            float* ringw = g_ring[l][t & 3];
#pragma unroll
            for (int it = 0; it < 2; ++it) {
                int b = bg + it * 16;
                float s0 = 0.f, s1 = 0.f, s2 = 0.f, s3 = 0.f;
#pragma unroll
                for (int q = 0; q < 4; ++q) {
                    s0 += part[(q * 64 +      col) * 33 + b];
                    s1 += part[(q * 64 + 16 + col) * 33 + b];
                    s2 += part[(q * 64 + 32 + col) * 33 + b];
                    s3 += part[(q * 64 + 48 + col) * 33 + b];
                }
                float si = fsigmoid(s0 + bsh[col]);
                float sf = fsigmoid(s1 + bsh[16 + col]);
                float tg = ftanh(s2 + bsh[32 + col]);
                float so = fsigmoid(s3 + bsh[48 + col]);
                float cc = (it ? c1 : c0);
                cc = sf * cc + si * tg;
                if (it) c1 = cc; else c0 = cc;
                float hn = so * ftanh(cc);
                ringw[(size_t)b * Hq + j0 + col] = hn;
                if (l == 3)
                    out3[((size_t)b * Sq + t) * Hq + j0 + col] = hn;
            }
        }
        __syncthreads();
        if (tid == 0) {
            unsigned val = (unsigned)(t + 1);
            asm volatile("membar.gl;" ::: "memory");
            asm volatile("st.release.gpu.global.u32 [%0], %1;"
                         :: "l"(&flg_own[cidx * 32]), "r"(val) : "memory");
        }
    }
}

// ---- softmax over sequence axis ----
__global__ void __launch_bounds__(256) softmax_kernel(
    const float* __restrict__ in, float* __restrict__ probs)
{
    int gw = (blockIdx.x * 256 + threadIdx.x) >> 5;
    int lane = threadIdx.x & 31;
    int bb = gw >> 9, hh = gw & 511;
    const float* p = in + (size_t)bb * Sq * Hq + hh;
    float v[8], mx = -3.4e38f;
#pragma unroll
    for (int i = 0; i < 8; ++i) {
        v[i] = p[(size_t)(lane + 32 * i) * Hq];
        mx = fmaxf(mx, v[i]);
    }
#pragma unroll
    for (int o = 16; o; o >>= 1) mx = fmaxf(mx, __shfl_xor_sync(~0u, mx, o));
    float sum = 0.f;
#pragma unroll
    for (int i = 0; i < 8; ++i) { v[i] = __expf(v[i] - mx); sum += v[i]; }
#pragma unroll
    for (int o = 16; o; o >>= 1) sum += __shfl_xor_sync(~0u, sum, o);
    float inv = 1.f / sum;
    float* q = probs + (size_t)bb * Sq * Hq + hh;
#pragma unroll
    for (int i = 0; i < 8; ++i) q[(size_t)(lane + 32 * i) * Hq] = v[i] * inv;
}

// ---- final FC ----
__global__ void __launch_bounds__(256) fc_kernel(
    const float* __restrict__ probs, const float* __restrict__ Wfc,
    const float* __restrict__ bfc, float* __restrict__ out)
{
    int gw = (blockIdx.x * 256 + threadIdx.x) >> 5;
    int lane = threadIdx.x & 31;
    const float* p = probs + (size_t)gw * Hq;
    float a0 = 0.f, a1 = 0.f, a2 = 0.f, a3 = 0.f;
    for (int k = lane; k < Hq; k += 32) {
        float pv = p[k];
        a0 += pv * Wfc[k];
        a1 += pv * Wfc[Hq + k];
        a2 += pv * Wfc[2 * Hq + k];
        a3 += pv * Wfc[3 * Hq + k];
    }
#pragma unroll
    for (int o = 16; o; o >>= 1) {
        a0 += __shfl_xor_sync(~0u, a0, o);
        a1 += __shfl_xor_sync(~0u, a1, o);
        a2 += __shfl_xor_sync(~0u, a2, o);
        a3 += __shfl_xor_sync(~0u, a3, o);
    }
    if (lane == 0) {
        float4 rr;
        rr.x = a0 + bfc[0]; rr.y = a1 + bfc[1];
        rr.z = a2 + bfc[2]; rr.w = a3 + bfc[3];
        *reinterpret_cast<float4*>(out + (size_t)gw * 4) = rr;
    }
}

// ---- launcher ----
extern "C" void kernel_launch(void* const* d_in, const int* in_sizes, int n_in,
                              void* d_out, int out_size)
{
    const float* x    = (const float*)d_in[0];
    const float* Wih0 = (const float*)d_in[1];
    const float* WihR = (const float*)d_in[2];
    const float* Whh  = (const float*)d_in[3];
    const float* bih  = (const float*)d_in[4];
    const float* bhh  = (const float*)d_in[5];
    const float* Wfc  = (const float*)d_in[6];
    const float* bfc  = (const float*)d_in[7];
    float* out = (float*)d_out;

    float *out3, *probs;
    cudaGetSymbolAddress((void**)&out3,  g_out3);
    cudaGetSymbolAddress((void**)&probs, g_probs);

    cudaFuncSetAttribute(lstm_fused_kernel,
                         cudaFuncAttributeMaxDynamicSharedMemorySize,
                         SMEM_BYTES);

    transpose_kernel<<<8192, 256>>>(Wih0, WihR, Whh);
    lstm_fused_kernel<<<128, TPB, SMEM_BYTES>>>(x, bih, bhh, out3);
    softmax_kernel<<<2048, 256>>>(out3, probs);
    fc_kernel<<<1024, 256>>>(probs, Wfc, bfc, out);
}